// round 2
// baseline (speedup 1.0000x reference)
#include <cuda_runtime.h>
#include <cuda_bf16.h>

// ---------------------------------------------------------------------------
// 2-layer GCN: h = relu(GCN(relu(GCN(x, W1, b1)), W2, b2))
// GCNConv: out = D^{-1/2}(A+I)D^{-1/2} X W + b
//
// NOTE: edge_index arrives as int32 (JAX demotes int64 without x64 mode).
//
// Pipeline (per call, graph-capturable, no allocations):
//   1. deg[i] = 1 + #edges with dst==i  ;  dinv[i] = rsqrt(deg[i])
//   2. layer: xw = X @ W
//             agg[i] = xw[i] * dinv[i]^2                 (self-loop term)
//             for each edge (s,d): agg[d] += xw[s] * dinv[s]*dinv[d]  (v4 RED)
//             h[i]   = relu(agg[i] + b)
// ---------------------------------------------------------------------------

#define MAX_N 50000
#define MAX_E 600000
#define H 128   // feature dim (in = hidden = 128)

// Scratch (static device globals; runtime allocation is forbidden)
__device__ float g_dinv[MAX_N];
__device__ float g_xw[MAX_N * H];
__device__ float g_agg[MAX_N * H];
__device__ float g_h[MAX_N * H];

// ---------------------------------------------------------------------------
// Degree / normalization
// ---------------------------------------------------------------------------
__global__ void deg_init_kernel(float* deg, int n) {
    int i = blockIdx.x * blockDim.x + threadIdx.x;
    if (i < n) deg[i] = 1.0f;  // self-loop
}

__global__ void deg_count_kernel(const int* __restrict__ ei, float* deg, int e) {
    int i = blockIdx.x * blockDim.x + threadIdx.x;
    if (i < e) {
        int d = ei[e + i];  // dst row
        atomicAdd(&deg[d], 1.0f);
    }
}

__global__ void dinv_kernel(float* deg, int n) {
    int i = blockIdx.x * blockDim.x + threadIdx.x;
    if (i < n) deg[i] = rsqrtf(deg[i]);  // in-place: g_dinv holds deg then dinv
}

// ---------------------------------------------------------------------------
// GEMM: C[N,128] = A[N,128] @ W[128,128]
// Block = 256 threads, computes 32 rows x 128 cols.
// Thread (col = tid&127, half = tid>>7) computes 16 rows for its column.
// All smem reads are warp-uniform broadcasts (conflict-free).
// ---------------------------------------------------------------------------
__global__ void __launch_bounds__(256) gemm128_kernel(
    const float* __restrict__ A, const float* __restrict__ W,
    float* __restrict__ C, int n)
{
    __shared__ float xs[32][H];
    const int tid = threadIdx.x;
    const int block_row = blockIdx.x * 32;

    // Load A tile [32 x 128] as float4: 32 rows x 32 float4 = 1024, 4 per thread.
    const float4* A4 = reinterpret_cast<const float4*>(A);
    float4* xs4 = reinterpret_cast<float4*>(&xs[0][0]);
#pragma unroll
    for (int i = tid; i < 32 * 32; i += 256) {
        int r = i >> 5;
        int c4 = i & 31;
        int row = block_row + r;
        float4 v = make_float4(0.f, 0.f, 0.f, 0.f);
        if (row < n) v = A4[row * 32 + c4];
        xs4[r * 32 + c4] = v;
    }
    __syncthreads();

    const int col = tid & 127;
    const int half = tid >> 7;  // 0 or 1
    float acc[16];
#pragma unroll
    for (int r = 0; r < 16; r++) acc[r] = 0.0f;

#pragma unroll 4
    for (int k = 0; k < H; k++) {
        float w = W[k * H + col];
#pragma unroll
        for (int r = 0; r < 16; r++) acc[r] += xs[half * 16 + r][k] * w;
    }

#pragma unroll
    for (int r = 0; r < 16; r++) {
        int row = block_row + half * 16 + r;
        if (row < n) C[row * H + col] = acc[r];
    }
}

// ---------------------------------------------------------------------------
// agg[i] = xw[i] * dinv[i]^2   (self-loop contribution, also zero-initializes)
// ---------------------------------------------------------------------------
__global__ void self_init_kernel(const float* __restrict__ xw,
                                 const float* __restrict__ dinv,
                                 float* __restrict__ agg, int n)
{
    int idx = blockIdx.x * blockDim.x + threadIdx.x;          // float4 index
    int total4 = n * (H / 4);
    if (idx < total4) {
        int row = idx >> 5;  // H/4 = 32 float4 per row
        float s = dinv[row];
        s = s * s;
        float4 v = reinterpret_cast<const float4*>(xw)[idx];
        v.x *= s; v.y *= s; v.z *= s; v.w *= s;
        reinterpret_cast<float4*>(agg)[idx] = v;
    }
}

// ---------------------------------------------------------------------------
// Edge scatter: one warp per edge; each lane handles one float4 (32*4 = 128).
// red.global.add.v4.f32 -> single vector reduction per lane, no return value.
// ---------------------------------------------------------------------------
__device__ __forceinline__ void red_add_v4(float4* addr, float4 v) {
    asm volatile("red.global.add.v4.f32 [%0], {%1, %2, %3, %4};"
                 :: "l"(addr), "f"(v.x), "f"(v.y), "f"(v.z), "f"(v.w)
                 : "memory");
}

__global__ void __launch_bounds__(256) edge_scatter_kernel(
    const int* __restrict__ ei,
    const float* __restrict__ dinv,
    const float* __restrict__ xw,
    float* __restrict__ agg, int e)
{
    int warp = (blockIdx.x * blockDim.x + threadIdx.x) >> 5;
    int lane = threadIdx.x & 31;
    if (warp >= e) return;

    int s = ei[warp];       // src
    int d = ei[e + warp];   // dst
    float norm = dinv[s] * dinv[d];

    float4 v = reinterpret_cast<const float4*>(xw + (size_t)s * H)[lane];
    v.x *= norm; v.y *= norm; v.z *= norm; v.w *= norm;
    red_add_v4(reinterpret_cast<float4*>(agg + (size_t)d * H) + lane, v);
}

// ---------------------------------------------------------------------------
// out[i][c] = relu(agg[i][c] + b[c])
// ---------------------------------------------------------------------------
__global__ void bias_relu_kernel(const float* __restrict__ agg,
                                 const float* __restrict__ b,
                                 float* __restrict__ out, int n)
{
    int idx = blockIdx.x * blockDim.x + threadIdx.x;  // float4 index
    int total4 = n * (H / 4);
    if (idx < total4) {
        int c4 = idx & 31;  // float4 column within row
        float4 v = reinterpret_cast<const float4*>(agg)[idx];
        float4 bb = reinterpret_cast<const float4*>(b)[c4];
        v.x = fmaxf(v.x + bb.x, 0.0f);
        v.y = fmaxf(v.y + bb.y, 0.0f);
        v.z = fmaxf(v.z + bb.z, 0.0f);
        v.w = fmaxf(v.w + bb.w, 0.0f);
        reinterpret_cast<float4*>(out)[idx] = v;
    }
}

// ---------------------------------------------------------------------------
// Launch
// ---------------------------------------------------------------------------
extern "C" void kernel_launch(void* const* d_in, const int* in_sizes, int n_in,
                              void* d_out, int out_size)
{
    const float* x  = (const float*)d_in[0];
    const int*   ei = (const int*)d_in[1];
    const float* W1 = (const float*)d_in[2];
    const float* b1 = (const float*)d_in[3];
    const float* W2 = (const float*)d_in[4];
    const float* b2 = (const float*)d_in[5];
    float* out = (float*)d_out;

    const int n = in_sizes[0] / H;       // 50000
    const int e = in_sizes[1] / 2;       // 600000

    float* dinv; cudaGetSymbolAddress((void**)&dinv, g_dinv);
    float* xw;   cudaGetSymbolAddress((void**)&xw,   g_xw);
    float* agg;  cudaGetSymbolAddress((void**)&agg,  g_agg);
    float* h;    cudaGetSymbolAddress((void**)&h,    g_h);

    const int T = 256;
    const int blocks_n    = (n + T - 1) / T;
    const int blocks_e    = (e + T - 1) / T;
    const int blocks_elem = (n * (H / 4) + T - 1) / T;
    const int blocks_gemm = (n + 31) / 32;
    const long long scat_threads = (long long)e * 32;
    const int blocks_scat = (int)((scat_threads + T - 1) / T);   // one warp per edge

    // degree + normalization
    deg_init_kernel<<<blocks_n, T>>>(dinv, n);
    deg_count_kernel<<<blocks_e, T>>>(ei, dinv, e);
    dinv_kernel<<<blocks_n, T>>>(dinv, n);

    // layer 1
    gemm128_kernel<<<blocks_gemm, T>>>(x, W1, xw, n);
    self_init_kernel<<<blocks_elem, T>>>(xw, dinv, agg, n);
    edge_scatter_kernel<<<blocks_scat, T>>>(ei, dinv, xw, agg, e);
    bias_relu_kernel<<<blocks_elem, T>>>(agg, b1, h, n);

    // layer 2
    gemm128_kernel<<<blocks_gemm, T>>>(h, W2, xw, n);
    self_init_kernel<<<blocks_elem, T>>>(xw, dinv, agg, n);
    edge_scatter_kernel<<<blocks_scat, T>>>(ei, dinv, xw, agg, e);
    bias_relu_kernel<<<blocks_elem, T>>>(agg, b2, out, n);
}

// round 3
// speedup vs baseline: 1.2527x; 1.2527x over previous
#include <cuda_runtime.h>
#include <cuda_bf16.h>

// ---------------------------------------------------------------------------
// 2-layer GCN: h = relu(GCN(relu(GCN(x, W1, b1)), W2, b2))
// GCNConv: out = D^{-1/2}(A+I)D^{-1/2} X W + b      (edge_index is int32)
//
// R3 changes:
//   * register-tiled GEMM (8 rows x 4 cols per thread) -> FFMA-bound
//   * self-loop term fused into GEMM epilogue (agg = xw * dinv^2)
// ---------------------------------------------------------------------------

#define MAX_N 50000
#define MAX_E 600000
#define H 128

__device__ float g_dinv[MAX_N];
__device__ float g_xw[MAX_N * H];
__device__ float g_agg[MAX_N * H];
__device__ float g_h[MAX_N * H];

// ---------------------------------------------------------------------------
// Degree / normalization
// ---------------------------------------------------------------------------
__global__ void deg_init_kernel(float* deg, int n) {
    int i = blockIdx.x * blockDim.x + threadIdx.x;
    if (i < n) deg[i] = 1.0f;  // self-loop
}

__global__ void deg_count_kernel(const int* __restrict__ ei, float* deg, int e) {
    int i = blockIdx.x * blockDim.x + threadIdx.x;
    if (i < e) atomicAdd(&deg[ei[e + i]], 1.0f);
}

__global__ void dinv_kernel(float* deg, int n) {
    int i = blockIdx.x * blockDim.x + threadIdx.x;
    if (i < n) deg[i] = rsqrtf(deg[i]);
}

// ---------------------------------------------------------------------------
// Fused GEMM + self-loop epilogue.
// C = A @ W ; xw <- C ; agg <- C * dinv^2
// Block: 256 threads -> 64 rows x 128 cols. Thread: 8 rows x 4 cols.
//   tx = tid&31  -> cols 4*tx .. 4*tx+3 (one float4)
//   ty = tid>>5  -> rows 8*ty .. 8*ty+7
// Inner loop per k: 1 LDS.128 (W) + 8 broadcast LDS (A rows) + 32 FFMA.
// ---------------------------------------------------------------------------
__global__ void __launch_bounds__(256) gemm128_fused_kernel(
    const float* __restrict__ A, const float* __restrict__ W,
    const float* __restrict__ dinv,
    float* __restrict__ xw, float* __restrict__ agg, int n)
{
    __shared__ float xs[64][H];    // 32 KB
    __shared__ float ws[32][H];    // 16 KB (K chunk of W)

    const int tid = threadIdx.x;
    const int row0 = blockIdx.x * 64;

    // Load A tile [64 x 128] as float4 (8 per thread), coalesced.
    const float4* A4 = reinterpret_cast<const float4*>(A);
#pragma unroll
    for (int i = tid; i < 64 * 32; i += 256) {
        int r = i >> 5, c4 = i & 31;
        int row = row0 + r;
        float4 v = make_float4(0.f, 0.f, 0.f, 0.f);
        if (row < n) v = A4[row * 32 + c4];
        reinterpret_cast<float4*>(&xs[r][0])[c4] = v;
    }

    const int tx = tid & 31;
    const int ty = tid >> 5;

    float acc[8][4];
#pragma unroll
    for (int r = 0; r < 8; r++)
#pragma unroll
        for (int c = 0; c < 4; c++) acc[r][c] = 0.f;

    const float4* W4 = reinterpret_cast<const float4*>(W);

#pragma unroll 1
    for (int kc = 0; kc < 4; kc++) {
        __syncthreads();
        // Load W rows [kc*32, kc*32+32): 32x32 float4, 4 per thread.
#pragma unroll
        for (int i = tid; i < 32 * 32; i += 256) {
            int r = i >> 5, c4 = i & 31;
            reinterpret_cast<float4*>(&ws[r][0])[c4] = W4[(kc * 32 + r) * 32 + c4];
        }
        __syncthreads();

#pragma unroll
        for (int k = 0; k < 32; k++) {
            float4 w4 = reinterpret_cast<float4*>(&ws[k][0])[tx];
            float a[8];
#pragma unroll
            for (int r = 0; r < 8; r++) a[r] = xs[ty * 8 + r][kc * 32 + k];
#pragma unroll
            for (int r = 0; r < 8; r++) {
                acc[r][0] += a[r] * w4.x;
                acc[r][1] += a[r] * w4.y;
                acc[r][2] += a[r] * w4.z;
                acc[r][3] += a[r] * w4.w;
            }
        }
    }

    // Epilogue: xw = C ; agg = C * dinv^2
#pragma unroll
    for (int r = 0; r < 8; r++) {
        int row = row0 + ty * 8 + r;
        if (row < n) {
            float4 v = make_float4(acc[r][0], acc[r][1], acc[r][2], acc[r][3]);
            reinterpret_cast<float4*>(xw + (size_t)row * H)[tx] = v;
            float s = dinv[row];
            s = s * s;
            float4 u = make_float4(v.x * s, v.y * s, v.z * s, v.w * s);
            reinterpret_cast<float4*>(agg + (size_t)row * H)[tx] = u;
        }
    }
}

// ---------------------------------------------------------------------------
// Edge scatter: one warp per edge; each lane one float4 (32*4 = 128 floats).
// ---------------------------------------------------------------------------
__device__ __forceinline__ void red_add_v4(float4* addr, float4 v) {
    asm volatile("red.global.add.v4.f32 [%0], {%1, %2, %3, %4};"
                 :: "l"(addr), "f"(v.x), "f"(v.y), "f"(v.z), "f"(v.w)
                 : "memory");
}

__global__ void __launch_bounds__(256) edge_scatter_kernel(
    const int* __restrict__ ei,
    const float* __restrict__ dinv,
    const float* __restrict__ xw,
    float* __restrict__ agg, int e)
{
    int warp = (blockIdx.x * blockDim.x + threadIdx.x) >> 5;
    int lane = threadIdx.x & 31;
    if (warp >= e) return;

    int s = ei[warp];
    int d = ei[e + warp];
    float norm = dinv[s] * dinv[d];

    float4 v = reinterpret_cast<const float4*>(xw + (size_t)s * H)[lane];
    v.x *= norm; v.y *= norm; v.z *= norm; v.w *= norm;
    red_add_v4(reinterpret_cast<float4*>(agg + (size_t)d * H) + lane, v);
}

// ---------------------------------------------------------------------------
// out[i][c] = relu(agg[i][c] + b[c])
// ---------------------------------------------------------------------------
__global__ void bias_relu_kernel(const float* __restrict__ agg,
                                 const float* __restrict__ b,
                                 float* __restrict__ out, int n)
{
    int idx = blockIdx.x * blockDim.x + threadIdx.x;
    int total4 = n * (H / 4);
    if (idx < total4) {
        int c4 = idx & 31;
        float4 v = reinterpret_cast<const float4*>(agg)[idx];
        float4 bb = reinterpret_cast<const float4*>(b)[c4];
        v.x = fmaxf(v.x + bb.x, 0.0f);
        v.y = fmaxf(v.y + bb.y, 0.0f);
        v.z = fmaxf(v.z + bb.z, 0.0f);
        v.w = fmaxf(v.w + bb.w, 0.0f);
        reinterpret_cast<float4*>(out)[idx] = v;
    }
}

// ---------------------------------------------------------------------------
// Launch
// ---------------------------------------------------------------------------
extern "C" void kernel_launch(void* const* d_in, const int* in_sizes, int n_in,
                              void* d_out, int out_size)
{
    const float* x  = (const float*)d_in[0];
    const int*   ei = (const int*)d_in[1];
    const float* W1 = (const float*)d_in[2];
    const float* b1 = (const float*)d_in[3];
    const float* W2 = (const float*)d_in[4];
    const float* b2 = (const float*)d_in[5];
    float* out = (float*)d_out;

    const int n = in_sizes[0] / H;       // 50000
    const int e = in_sizes[1] / 2;       // 600000

    float* dinv; cudaGetSymbolAddress((void**)&dinv, g_dinv);
    float* xw;   cudaGetSymbolAddress((void**)&xw,   g_xw);
    float* agg;  cudaGetSymbolAddress((void**)&agg,  g_agg);
    float* h;    cudaGetSymbolAddress((void**)&h,    g_h);

    const int T = 256;
    const int blocks_n    = (n + T - 1) / T;
    const int blocks_e    = (e + T - 1) / T;
    const int blocks_elem = (n * (H / 4) + T - 1) / T;
    const int blocks_gemm = (n + 63) / 64;
    const long long scat_threads = (long long)e * 32;
    const int blocks_scat = (int)((scat_threads + T - 1) / T);

    // degree + normalization
    deg_init_kernel<<<blocks_n, T>>>(dinv, n);
    deg_count_kernel<<<blocks_e, T>>>(ei, dinv, e);
    dinv_kernel<<<blocks_n, T>>>(dinv, n);

    // layer 1
    gemm128_fused_kernel<<<blocks_gemm, T>>>(x, W1, dinv, xw, agg, n);
    edge_scatter_kernel<<<blocks_scat, T>>>(ei, dinv, xw, agg, e);
    bias_relu_kernel<<<blocks_elem, T>>>(agg, b1, h, n);

    // layer 2
    gemm128_fused_kernel<<<blocks_gemm, T>>>(h, W2, dinv, xw, agg, n);
    edge_scatter_kernel<<<blocks_scat, T>>>(ei, dinv, xw, agg, e);
    bias_relu_kernel<<<blocks_elem, T>>>(agg, b2, out, n);
}